// round 16
// baseline (speedup 1.0000x reference)
#include <cuda_runtime.h>
#include <cuda_fp16.h>
#include <math.h>
#include <stdint.h>

// ---------------- problem constants ----------------
#define Bc   2
#define Sc   1024
#define Hc   1024
#define Ic   2048
#define Nst  16
#define Rc   64
#define Kcv  4
#define NHc  16
#define NKVc 4
#define HDc  64
#define WATT 512
#define WSSM 128
#define IMc  2816
#define Mrows (Bc*Sc)
#define EPSc  1e-6f
#define PROJW (Rc + 2*Nst)   // 96
#define FUSN  5632
#define KVSLD 512
#define GATEN 5632

// ---------------- scratch ----------------
__device__ __half g_hs[Mrows*Hc];
__device__ __half g_xzq[Mrows*FUSN];
__device__ float  g_xs[Mrows*Ic];
__device__ __half g_xsh[Mrows*Ic];
__device__ __half g_proj_h[Mrows*PROJW];
__device__ float  g_dt[Mrows*Ic];
__device__ __half g_y[Mrows*Ic];
__device__ float  g_tmp[Mrows*Hc];
__device__ float  g_ssmres[Mrows*Hc];
__device__ __half g_ssmst[Mrows*Hc];
__device__ float  g_kvssm[Mrows*KVSLD];
__device__ __half g_oh[Mrows*NHc*HDc];
__device__ float  g_mlpres[Mrows*Hc];
__device__ __half g_x2[Mrows*Hc];
__device__ __half g_hm[Mrows*IMc];
// compact half attention operands
__device__ __half g_qh[Mrows*NHc*HDc];
__device__ __half g_kah[Mrows*NKVc*HDc];
__device__ __half g_ksh[Mrows*NKVc*HDc];
__device__ __half g_vah[Mrows*NKVc*HDc];
__device__ __half g_vsh[Mrows*NKVc*HDc];
// split-softmax state
__device__ float  g_ml[Mrows*NHc*2];
__device__ float  g_opart[Mrows*NHc*HDc];
// half weights
__device__ __half g_wbig[FUSN*Hc];
__device__ __half g_wxp[PROJW*Ic];
__device__ __half g_wdt[Ic*Rc];
__device__ __half g_wop[Hc*Ic];
__device__ __half g_wkv[KVSLD*Hc];
__device__ __half g_wo[Hc*NHc*HDc];
__device__ __half g_wg[GATEN*Hc];
__device__ __half g_wd[Hc*IMc];

__device__ __forceinline__ float fsig(float x) { return 1.f / (1.f + __expf(-x)); }

// ---------------- fp16 MMA GEMM ----------------
#define BM 128
#define BK 32
#define PADH 40
#define STAGES 4

#define OP_NONE   0
#define OP_HALF   1
#define OP_SPLUS  2
#define OP_SWIGLU 3
#define OP_ADDC   4

__device__ __forceinline__ void cp16(uint32_t dst, const void* src, int ssize) {
    asm volatile("cp.async.cg.shared.global [%0], [%1], 16, %2;\n"
                 :: "r"(dst), "l"(src), "r"(ssize));
}
__device__ __forceinline__ void mma_f16(float* c, const uint32_t* a, uint32_t b0, uint32_t b1) {
    asm volatile("mma.sync.aligned.m16n8k16.row.col.f32.f16.f16.f32 "
                 "{%0,%1,%2,%3}, {%4,%5,%6,%7}, {%8,%9}, {%0,%1,%2,%3};\n"
                 : "+f"(c[0]), "+f"(c[1]), "+f"(c[2]), "+f"(c[3])
                 : "r"(a[0]), "r"(a[1]), "r"(a[2]), "r"(a[3]), "r"(b0), "r"(b1));
}

template<int BNT, int OP, bool NG>
__global__ __launch_bounds__(128, 2)
void gemm_h(const __half* __restrict__ A, const __half* __restrict__ Bw,
            void* __restrict__ Cv, const float* __restrict__ aux,
            int Ndim, int Kdim, int lda, int ldb) {
    constexpr int NI  = BNT / 16;
    constexpr int ASZ = BM * PADH;
    constexpr int BSZ = BNT * PADH;
    constexpr int STG = ASZ + BSZ;
    extern __shared__ __half smh[];
    const int t    = threadIdx.x;
    const int bm   = blockIdx.y * BM;
    const int bn   = blockIdx.x * BNT;
    const int warp = t >> 5, lane = t & 31;
    const int wm   = (warp & 1) * 64;
    const int wn   = (warp >> 1) * (BNT / 2);
    const int gid  = lane >> 2;
    const int tig  = lane & 3;
    const uint32_t smem_base = (uint32_t)__cvta_generic_to_shared(smh);

    float acc[4][NI][4];
#pragma unroll
    for (int mi = 0; mi < 4; mi++)
#pragma unroll
        for (int ni = 0; ni < NI; ni++)
#pragma unroll
            for (int j = 0; j < 4; j++) acc[mi][ni][j] = 0.f;

    const int niters = Kdim / BK;

    auto load_tile = [&](int slot, int k0) {
        uint32_t aOff = smem_base + slot * STG * 2;
        uint32_t bOff = aOff + ASZ * 2;
#pragma unroll
        for (int i = 0; i < 4; i++) {
            int id = t + i * 128;
            int r  = id >> 2;
            int kq = (id & 3) * 8;
            cp16(aOff + (r * PADH + kq) * 2, A + (size_t)(bm + r) * lda + k0 + kq, 16);
        }
#pragma unroll
        for (int i = 0; i < BNT / 32; i++) {
            int id = t + i * 128;
            int r  = id >> 2;
            int kq = (id & 3) * 8;
            int ok = 1;
            int br = bn + r;
            if (NG) ok = (br < Ndim);
            cp16(bOff + (r * PADH + kq) * 2,
                 Bw + (size_t)(NG ? (ok ? br : 0) : br) * ldb + k0 + kq, ok ? 16 : 0);
        }
    };

#pragma unroll
    for (int s = 0; s < STAGES - 1; s++) {
        if (s < niters) load_tile(s, s * BK);
        asm volatile("cp.async.commit_group;\n");
    }

    int cslot = 0, nslot = STAGES - 1;
    for (int it = 0; it < niters; it++) {
        asm volatile("cp.async.wait_group %0;\n" :: "n"(STAGES - 2));
        __syncthreads();
        int nk = it + STAGES - 1;
        if (nk < niters) load_tile(nslot, nk * BK);
        asm volatile("cp.async.commit_group;\n");
        if (++nslot == STAGES) nslot = 0;

        const __half* Ab = smh + cslot * STG;
        const __half* Bb = Ab + ASZ;
        if (++cslot == STAGES) cslot = 0;
#pragma unroll
        for (int kk = 0; kk < 2; kk++) {
            int kb = kk * 16;
            uint32_t afr[4][4];
#pragma unroll
            for (int mi = 0; mi < 4; mi++) {
                const __half* ab = Ab + (wm + mi * 16 + gid) * PADH + kb + tig * 2;
                afr[mi][0] = *(const uint32_t*)(ab);
                afr[mi][1] = *(const uint32_t*)(ab + 8 * PADH);
                afr[mi][2] = *(const uint32_t*)(ab + 8);
                afr[mi][3] = *(const uint32_t*)(ab + 8 * PADH + 8);
            }
#pragma unroll
            for (int ni = 0; ni < NI; ni++) {
                const __half* bb = Bb + (wn + ni * 8 + gid) * PADH + kb + tig * 2;
                uint32_t b0 = *(const uint32_t*)(bb);
                uint32_t b1 = *(const uint32_t*)(bb + 8);
#pragma unroll
                for (int mi = 0; mi < 4; mi++)
                    mma_f16(acc[mi][ni], afr[mi], b0, b1);
            }
        }
    }

    float*  Cf = (float*)Cv;
    __half* Ch = (__half*)Cv;
#pragma unroll
    for (int mi = 0; mi < 4; mi++) {
        int rbase = bm + wm + mi * 16 + gid;
#pragma unroll
        for (int ni = 0; ni < NI; ni++) {
            int c0 = bn + wn + ni * 8 + tig * 2;
            if (NG && c0 >= Ndim) continue;
#pragma unroll
            for (int half_ = 0; half_ < 2; half_++) {
                int r0 = rbase + half_ * 8;
                float a0 = acc[mi][ni][half_ * 2 + 0];
                float a1 = acc[mi][ni][half_ * 2 + 1];
                if (OP == OP_NONE) {
                    *(float2*)(Cf + (size_t)r0 * Ndim + c0) = make_float2(a0, a1);
                } else if (OP == OP_HALF) {
                    *(__half2*)(Ch + (size_t)r0 * Ndim + c0) = __floats2half2_rn(a0, a1);
                } else if (OP == OP_SPLUS) {
                    float x0 = a0 + aux[c0], x1 = a1 + aux[c0 + 1];
                    x0 = (x0 > 20.f) ? x0 : __logf(1.f + __expf(x0));
                    x1 = (x1 > 20.f) ? x1 : __logf(1.f + __expf(x1));
                    *(float2*)(Cf + (size_t)r0 * Ndim + c0) = make_float2(x0, x1);
                } else if (OP == OP_SWIGLU) {
                    float sv = a0 * fsig(a0) * a1;
                    Ch[(size_t)r0 * IMc + (c0 >> 1)] = __float2half_rn(sv);
                } else if (OP == OP_ADDC) {
                    float2 r = *(const float2*)(aux + (size_t)r0 * Ndim + c0);
                    *(float2*)(Cf + (size_t)r0 * Ndim + c0) =
                        make_float2(a0 + r.x, a1 + r.y);
                }
            }
        }
    }
}

// ---------------- fused prep + prenorm ----------------
#define W0 (FUSN*Hc)
#define R1 (KVSLD*Hc)
#define R2 (R1 + GATEN*Hc)
#define R3 (R2 + PROJW*Ic)
#define R4 (R3 + Ic*Rc)
#define R5 (R4 + Hc*Ic)
#define R6 (R5 + Hc*NHc*HDc)
#define R7 (R6 + Hc*IMc)
#define PREP_BLOCKS ((W0 + R7 + 255) / 256)

__global__ void k_prep_norm(const float* __restrict__ hidden, const float* __restrict__ pnw,
                            const float* __restrict__ ipw, const float* __restrict__ qw,
                            const float* __restrict__ kw, const float* __restrict__ vw,
                            const float* __restrict__ gw, const float* __restrict__ xpw,
                            const float* __restrict__ dtw, const float* __restrict__ opw,
                            const float* __restrict__ ow, const float* __restrict__ dw) {
    if (blockIdx.x < Mrows) {
        // prenorm row
        int row = blockIdx.x;
        int t   = threadIdx.x;
        const float* ap = hidden + (size_t)row * Hc;
        float v[4];
        float ss = 0.f;
#pragma unroll
        for (int i = 0; i < 4; i++) {
            int c = t + i * 256;
            float x = ap[c];
            v[i] = x;
            ss += x * x;
        }
#pragma unroll
        for (int off = 16; off; off >>= 1) ss += __shfl_xor_sync(0xffffffffu, ss, off);
        __shared__ float sred[8];
        __shared__ float sscale;
        if ((t & 31) == 0) sred[t >> 5] = ss;
        __syncthreads();
        if (t == 0) {
            float tot = 0.f;
            for (int i = 0; i < 8; i++) tot += sred[i];
            sscale = rsqrtf(tot * (1.f / Hc) + EPSc);
        }
        __syncthreads();
        float scale = sscale;
        __half* no = g_hs + (size_t)row * Hc;
#pragma unroll
        for (int i = 0; i < 4; i++) {
            int c = t + i * 256;
            no[c] = __float2half_rn(v[i] * scale * pnw[c]);
        }
        return;
    }
    int idx = (blockIdx.x - Mrows) * 256 + threadIdx.x;
    if (idx >= W0 + R7) return;
    if (idx < W0) {
        int row = idx >> 10, col = idx & 1023;
        float v;
        if (row < 4096)      v = ipw[idx];
        else if (row < 5120) v = qw[(row - 4096) * Hc + col];
        else if (row < 5376) v = kw[(row - 5120) * Hc + col];
        else                 v = vw[(row - 5376) * Hc + col];
        g_wbig[idx] = __float2half_rn(v);
        return;
    }
    idx -= W0;
    if (idx < R1) {
        int row = idx >> 10, col = idx & 1023;
        float v = (row < 256) ? kw[row * Hc + col] : vw[(row - 256) * Hc + col];
        g_wkv[idx] = __float2half_rn(v);
    } else if (idx < R2) {
        int i = idx - R1;
        int row = i >> 10, col = i & 1023;
        int f = row >> 1;
        int src = (row & 1) ? (IMc + f) : f;
        g_wg[i] = __float2half_rn(gw[src * Hc + col]);
    } else if (idx < R3) {
        int i = idx - R2; g_wxp[i] = __float2half_rn(xpw[i]);
    } else if (idx < R4) {
        int i = idx - R3; g_wdt[i] = __float2half_rn(dtw[i]);
    } else if (idx < R5) {
        int i = idx - R4; g_wop[i] = __float2half_rn(opw[i]);
    } else if (idx < R6) {
        int i = idx - R5; g_wo[i] = __float2half_rn(ow[i]);
    } else {
        int i = idx - R6; g_wd[i] = __float2half_rn(dw[i]);
    }
}

// ---------------- RMSNorm (standalone, residual variants) ----------------
__global__ void resid_rms(const float* __restrict__ a, const float* __restrict__ r,
                          const float* __restrict__ w, float* __restrict__ res_out,
                          __half* __restrict__ nrm_out) {
    int row = blockIdx.x;
    int t   = threadIdx.x;
    const float* ap = a + (size_t)row * Hc;
    const float* rp = r + (size_t)row * Hc;
    float v[4];
    float ss = 0.f;
#pragma unroll
    for (int i = 0; i < 4; i++) {
        int c = t + i * 256;
        float x = ap[c] + rp[c];
        v[i] = x;
        ss += x * x;
    }
#pragma unroll
    for (int off = 16; off; off >>= 1) ss += __shfl_xor_sync(0xffffffffu, ss, off);
    __shared__ float sred[8];
    __shared__ float sscale;
    if ((t & 31) == 0) sred[t >> 5] = ss;
    __syncthreads();
    if (t == 0) {
        float tot = 0.f;
        for (int i = 0; i < 8; i++) tot += sred[i];
        sscale = rsqrtf(tot * (1.f / Hc) + EPSc);
    }
    __syncthreads();
    float scale = sscale;
    float* ro = res_out + (size_t)row * Hc;
    __half* no = nrm_out + (size_t)row * Hc;
#pragma unroll
    for (int i = 0; i < 4; i++) {
        int c = t + i * 256;
        ro[c] = v[i];
        no[c] = __float2half_rn(v[i] * scale * w[c]);
    }
}

// ---------------- fused conv + postprocA (q/k_att rotary + v_att copy) ----------------
#define CONV_BLOCKS ((Mrows * Ic) / 256)          // 16384
#define PPA_W 896                                  // 512 q + 128 katt + 256 vatt
#define PPA_BLOCKS ((Mrows * PPA_W) / 256)        // 7168
__global__ void k_conv_ppa(const float* __restrict__ cw, const float* __restrict__ cb) {
    if (blockIdx.x < CONV_BLOCKS) {
        int idx = blockIdx.x * 256 + threadIdx.x;
        int row = idx / Ic;
        int i   = idx - row * Ic;
        int b   = row / Sc;
        int s   = row - b * Sc;
        float acc = cb[i];
#pragma unroll
        for (int k = 0; k < Kcv; k++) {
            int sp = s + k - (Kcv - 1);
            if (sp >= 0)
                acc += cw[i * Kcv + k] *
                       __half2float(g_xzq[(size_t)(b * Sc + sp) * FUSN + i]);
        }
        float r = acc * fsig(acc);
        g_xs[idx]  = r;
        g_xsh[idx] = __float2half_rn(r);
        return;
    }
    int idx = (blockIdx.x - CONV_BLOCKS) * 256 + threadIdx.x;
    int r   = idx / PPA_W;
    int rem = idx - r * PPA_W;
    int s   = r % Sc;
    if (rem < 512) {            // rotary q
        int head = rem >> 5, j = rem & 31;
        float inv = __expf(-((float)(2 * j) / 64.f) * __logf(10000.0f));
        float sn, cs; __sincosf((float)s * inv, &sn, &cs);
        const __half* bi = g_xzq + (size_t)r * FUSN + 4096 + head * HDc;
        __half* bo = g_qh + (size_t)r * 1024 + head * HDc;
        float x1 = __half2float(bi[j]), x2 = __half2float(bi[j + 32]);
        bo[j]      = __float2half_rn(x1 * cs - x2 * sn);
        bo[j + 32] = __float2half_rn(x2 * cs + x1 * sn);
    } else if (rem < 640) {     // rotary k_att
        int q = rem - 512;
        int head = q >> 5, j = q & 31;
        float inv = __expf(-((float)(2 * j) / 64.f) * __logf(10000.0f));
        float sn, cs; __sincosf((float)s * inv, &sn, &cs);
        const __half* bi = g_xzq + (size_t)r * FUSN + 5120 + head * HDc;
        __half* bo = g_kah + (size_t)r * 256 + head * HDc;
        float x1 = __half2float(bi[j]), x2 = __half2float(bi[j + 32]);
        bo[j]      = __float2half_rn(x1 * cs - x2 * sn);
        bo[j + 32] = __float2half_rn(x2 * cs + x1 * sn);
    } else {                    // v_att copy
        int col = rem - 640;
        g_vah[r * 256 + col] = g_xzq[(size_t)r * FUSN + 5376 + col];
    }
}

// ---------------- postprocB: k_ssm rotary + v_ssm copy ----------------
#define PPB_W 384
__global__ void postprocB() {
    int idx = blockIdx.x * 256 + threadIdx.x;
    int r   = idx / PPB_W;
    int rem = idx - r * PPB_W;
    int s   = r % Sc;
    if (rem < 128) {
        int head = rem >> 5, j = rem & 31;
        float inv = __expf(-((float)(2 * j) / 64.f) * __logf(10000.0f));
        float sn, cs; __sincosf((float)s * inv, &sn, &cs);
        const float* bi = g_kvssm + (size_t)r * KVSLD + head * HDc;
        __half* bo = g_ksh + (size_t)r * 256 + head * HDc;
        float x1 = bi[j], x2 = bi[j + 32];
        bo[j]      = __float2half_rn(x1 * cs - x2 * sn);
        bo[j + 32] = __float2half_rn(x2 * cs + x1 * sn);
    } else {
        int col = rem - 128;
        g_vsh[r * 256 + col] =
            __float2half_rn(g_kvssm[(size_t)r * KVSLD + 256 + col]);
    }
}

// ---------------- attention bodies ----------------
// attn_a: att window only; stores unnormalized O + (m, l).
__device__ void attn_a_body(int id, char* sm) {
    __half (*Kt)[72] = (__half(*)[72])sm;
    __half (*Vt)[72] = (__half(*)[72])(sm + 9216);
    int t = threadIdx.x;
    int w = t >> 5, lane = t & 31;
    int g = lane >> 2, tig = lane & 3;
    int qb = id & 15, h = (id >> 4) & 15, b = id >> 8;
    int q0 = qb * 64;
    int rowb = b * Sc, hk = h >> 2;
    int qr0 = q0 + w * 16 + g;
    int qr1 = qr0 + 8;

    uint32_t qf[4][4];
    {
        const __half* qb_ = g_qh + (size_t)rowb * 1024 + h * HDc;
#pragma unroll
        for (int kk = 0; kk < 4; kk++) {
            const __half* r0 = qb_ + (size_t)qr0 * 1024 + kk * 16 + tig * 2;
            const __half* r1 = qb_ + (size_t)qr1 * 1024 + kk * 16 + tig * 2;
            qf[kk][0] = *(const uint32_t*)(r0);
            qf[kk][1] = *(const uint32_t*)(r1);
            qf[kk][2] = *(const uint32_t*)(r0 + 8);
            qf[kk][3] = *(const uint32_t*)(r1 + 8);
        }
    }

    float O[8][4];
#pragma unroll
    for (int nt = 0; nt < 8; nt++)
#pragma unroll
        for (int e = 0; e < 4; e++) O[nt][e] = 0.f;
    float m0 = -1e30f, m1 = -1e30f, l0 = 0.f, l1 = 0.f;

    int cs = max(0, q0 - (WATT - 1)) & ~63;
    for (int c = q0; c >= cs; c -= 64) {
        __syncthreads();
#pragma unroll
        for (int i = 0; i < 4; i++) {
            int id2 = t + i * 128;
            int r  = id2 >> 3;
            int c8 = (id2 & 7) * 8;
            size_t src = (size_t)(rowb + c + r) * 256 + hk * HDc + c8;
            *(uint4*)&Kt[r][c8] = *(const uint4*)(g_kah + src);
            uint4 vv = *(const uint4*)(g_vah + src);
            const __half* hv = (const __half*)&vv;
#pragma unroll
            for (int j = 0; j < 8; j++) Vt[c8 + j][r] = hv[j];
        }
        __syncthreads();

        float S[8][4];
#pragma unroll
        for (int nt = 0; nt < 8; nt++)
#pragma unroll
            for (int e = 0; e < 4; e++) S[nt][e] = 0.f;
#pragma unroll
        for (int kk = 0; kk < 4; kk++)
#pragma unroll
            for (int nt = 0; nt < 8; nt++) {
                const __half* kp = &Kt[nt * 8 + g][kk * 16 + tig * 2];
                uint32_t b0 = *(const uint32_t*)kp;
                uint32_t b1 = *(const uint32_t*)(kp + 8);
                mma_f16(S[nt], qf[kk], b0, b1);
            }

        float mt0 = -1e30f, mt1 = -1e30f;
#pragma unroll
        for (int nt = 0; nt < 8; nt++) {
            int key = c + nt * 8 + tig * 2;
            float s0 = (key     <= qr0 && key     > qr0 - WATT) ? S[nt][0] * 0.125f : -1e30f;
            float s1 = (key + 1 <= qr0 && key + 1 > qr0 - WATT) ? S[nt][1] * 0.125f : -1e30f;
            float s2 = (key     <= qr1 && key     > qr1 - WATT) ? S[nt][2] * 0.125f : -1e30f;
            float s3 = (key + 1 <= qr1 && key + 1 > qr1 - WATT) ? S[nt][3] * 0.125f : -1e30f;
            S[nt][0] = s0; S[nt][1] = s1; S[nt][2] = s2; S[nt][3] = s3;
            mt0 = fmaxf(mt0, fmaxf(s0, s1));
            mt1 = fmaxf(mt1, fmaxf(s2, s3));
        }
        mt0 = fmaxf(mt0, __shfl_xor_sync(0xffffffffu, mt0, 1));
        mt0 = fmaxf(mt0, __shfl_xor_sync(0xffffffffu, mt0, 2));
        mt1 = fmaxf(mt1, __shfl_xor_sync(0xffffffffu, mt1, 1));
        mt1 = fmaxf(mt1, __shfl_xor_sync(0xffffffffu, mt1, 2));

        float nm0 = fmaxf(m0, mt0), nm1 = fmaxf(m1, mt1);
        float cr0 = __expf(m0 - nm0), cr1 = __expf(m1 - nm1);
        m0 = nm0; m1 = nm1;

        float ps0 = 0.f, ps1 = 0.f;
#pragma unroll
        for (int nt = 0; nt < 8; nt++) {
            S[nt][0] = __expf(S[nt][0] - nm0);
            S[nt][1] = __expf(S[nt][1] - nm0);
            S[nt][2] = __expf(S[nt][2] - nm1);
            S[nt][3] = __expf(S[nt][3] - nm1);
            ps0 += S[nt][0] + S[nt][1];
            ps1 += S[nt][2] + S[nt][3];
        }
        ps0 += __shfl_xor_sync(0xffffffffu, ps0, 1);
        ps0 += __shfl_xor_sync(0xffffffffu, ps0, 2);
        ps1 += __shfl_xor_sync(0xffffffffu, ps1, 1);
        ps1 += __shfl_xor_sync(0xffffffffu, ps1, 2);
        l0 = l0 * cr0 + ps0;
        l1 = l1 * cr1 + ps1;

#pragma unroll
        for (int nt = 0; nt < 8; nt++) {
            O[nt][0] *= cr0; O[nt][1] *= cr0;
            O[nt][2] *= cr1; O[nt][3] *= cr1;
        }

#pragma unroll
        for (int kk = 0; kk < 4; kk++) {
            uint32_t pf[4];
            __half2 h0 = __floats2half2_rn(S[2 * kk][0],     S[2 * kk][1]);
            __half2 h1 = __floats2half2_rn(S[2 * kk][2],     S[2 * kk][3]);
            __half2 h2 = __floats2half2_rn(S[2 * kk + 1][0], S[2 * kk + 1][1]);
            __half2 h3 = __floats2half2_rn(S[2 * kk + 1][2], S[2 * kk + 1][3]);
            pf[0] = *(uint32_t*)&h0; pf[1] = *(uint32_t*)&h1;
            pf[2] = *(uint32_t*)&h2; pf[3] = *(uint32_t*)&h3;
#pragma unroll
            for (int nt = 0; nt < 8; nt++) {
                const __half* vp = &Vt[nt * 8 + g][kk * 16 + tig * 2];
                uint32_t b0 = *(const uint32_t*)vp;
                uint32_t b1 = *(const uint32_t*)(vp + 8);
                mma_f16(O[nt], pf, b0, b1);
            }
        }
    }

    // store state
    size_t s0 = ((size_t)(rowb + qr0) * 16 + h);
    size_t s1 = ((size_t)(rowb + qr1) * 16 + h);
    if (tig == 0) {
        g_ml[s0 * 2] = m0; g_ml[s0 * 2 + 1] = l0;
        g_ml[s1 * 2] = m1; g_ml[s1 * 2 + 1] = l1;
    }
#pragma unroll
    for (int nt = 0; nt < 8; nt++) {
        *(float2*)(g_opart + s0 * 64 + nt * 8 + tig * 2) = make_float2(O[nt][0], O[nt][1]);
        *(float2*)(g_opart + s1 * 64 + nt * 8 + tig * 2) = make_float2(O[nt][2], O[nt][3]);
    }
}

// scan body (uses dynamic shared carve)
#define SCH 64
__device__ void scan_body(int blk, char* sm, const float* A_log, const float* Dp) {
    float  (*sdt)[SCH][16] = (float(*)[SCH][16])(sm);
    float  (*sxs)[SCH][16] = (float(*)[SCH][16])(sm + 8192);
    __half (*szz)[SCH][16] = (__half(*)[SCH][16])(sm + 16384);
    __half (*sbc)[SCH][32] = (__half(*)[SCH][32])(sm + 20480);
    __half (*sy)[16]       = (__half(*)[16])(sm + 28672);
    int t  = threadIdx.x;
    int gi0 = blk * 16;
    int b   = gi0 / Ic;
    int i0  = gi0 - b * Ic;
    int rowb = b * Sc;
    int c = t >> 4, n = t & 15;
    int i = i0 + c;
    float An = -__expf(A_log[i * Nst + n]);
    float Dv = Dp[i];

    int lrow = t >> 2, lq = t & 3;
    auto load_chunk = [&](int buf, int s0) {
        size_t gr = (size_t)(rowb + s0 + lrow);
        cp16((uint32_t)__cvta_generic_to_shared(&sdt[buf][lrow][lq * 4]),
             g_dt + gr * Ic + i0 + lq * 4, 16);
        cp16((uint32_t)__cvta_generic_to_shared(&sxs[buf][lrow][lq * 4]),
             g_xs + gr * Ic + i0 + lq * 4, 16);
        if (lq < 2)
            cp16((uint32_t)__cvta_generic_to_shared(&szz[buf][lrow][lq * 8]),
                 g_xzq + gr * FUSN + Ic + i0 + lq * 8, 16);
        cp16((uint32_t)__cvta_generic_to_shared(&sbc[buf][lrow][lq * 8]),
             g_proj_h + gr * PROJW + Rc + lq * 8, 16);
    };

    load_chunk(0, 0);
    asm volatile("cp.async.commit_group;\n");

    float h = 0.f;
    for (int ch = 0; ch < Sc / SCH; ch++) {
        int buf = ch & 1;
        if (ch + 1 < Sc / SCH) {
            load_chunk(buf ^ 1, (ch + 1) * SCH);
            asm volatile("cp.async.commit_group;\n");
            asm volatile("cp.async.wait_group 1;\n");
        } else {
            asm volatile("cp.async.wait_group 0;\n");
        }
        __syncthreads();
#pragma unroll 4
        for (int s = 0; s < SCH; s++) {
            float dtv = sdt[buf][s][c];
            float xsv = sxs[buf][s][c];
            float Bn  = __half2float(sbc[buf][s][n]);
            float Cn  = __half2float(sbc[buf][s][16 + n]);
            h = h * __expf(dtv * An) + dtv * Bn * xsv;
            float v = h * Cn;
            v += __shfl_xor_sync(0xffffffffu, v, 8);
            v += __shfl_xor_sync(0xffffffffu, v, 4);
            v += __shfl_xor_sync(0xffffffffu, v, 2);
            v += __shfl_xor_sync(0xffffffffu, v, 1);
            if (n == 0) {
                float z = __half2float(szz[buf][s][c]);
                sy[s][c] = __float2half_rn((v + Dv * xsv) * (z * fsig(z)));
            }
        }
        __syncthreads();
        if (t < 128) {
            int row = t >> 1, part = (t & 1) * 8;
            *(uint4*)(g_y + (size_t)(rowb + ch * SCH + row) * Ic + i0 + part) =
                *(const uint4*)&sy[row][part];
        }
    }
}

#define SCAN_BLOCKS ((Bc * Ic) / 16)   // 256
#define ATTA_BLOCKS (16 * NHc * Bc)    // 512
#define FUS_SMEM 30720
__global__ __launch_bounds__(256) void fused_scan_attn(const float* __restrict__ A_log,
                                                       const float* __restrict__ Dp) {
    extern __shared__ char smc[];
    if (blockIdx.x < SCAN_BLOCKS) {
        scan_body(blockIdx.x, smc, A_log, Dp);
    } else {
        if (threadIdx.x >= 128) return;   // attn body uses 128 threads
        attn_a_body(blockIdx.x - SCAN_BLOCKS, smc);
    }
}

// attn_b: continue with ssm window, merge, finalize.
__global__ __launch_bounds__(128) void attn_b() {
    __shared__ __half Kt[64][72];
    __shared__ __half Vt[64][72];
    int t = threadIdx.x, w = t >> 5, lane = t & 31;
    int g = lane >> 2, tig = lane & 3;
    int q0 = blockIdx.x * 64, h = blockIdx.y, b = blockIdx.z;
    int rowb = b * Sc, hk = h >> 2;
    int qr0 = q0 + w * 16 + g;
    int qr1 = qr0 + 8;

    uint32_t qf[4][4];
    {
        const __half* qb_ = g_qh + (size_t)rowb * 1024 + h * HDc;
#pragma unroll
        for (int kk = 0; kk < 4; kk++) {
            const __half* r0 = qb_ + (size_t)qr0 * 1024 + kk * 16 + tig * 2;
            const __half* r1 = qb_ + (size_t)qr1 * 1024 + kk * 16 + tig * 2;
            qf[kk][0] = *(const uint32_t*)(r0);
            qf[kk][1] = *(const uint32_t*)(r1);
            qf[kk][2] = *(const uint32_t*)(r0 + 8);
            qf[kk][3] = *(const uint32_t*)(r1 + 8);
        }
    }

    size_t st0 = ((size_t)(rowb + qr0) * 16 + h);
    size_t st1 = ((size_t)(rowb + qr1) * 16 + h);
    float m0 = g_ml[st0 * 2], l0 = g_ml[st0 * 2 + 1];
    float m1 = g_ml[st1 * 2], l1 = g_ml[st1 * 2 + 1];
    float O[8][4];
#pragma unroll
    for (int nt = 0; nt < 8; nt++) {
        float2 a = *(const float2*)(g_opart + st0 * 64 + nt * 8 + tig * 2);
        float2 c = *(const float2*)(g_opart + st1 * 64 + nt * 8 + tig * 2);
        O[nt][0] = a.x; O[nt][1] = a.y; O[nt][2] = c.x; O[nt][3] = c.y;
    }

    int cs = max(0, q0 - (WSSM - 1)) & ~63;
    for (int c = q0; c >= cs; c -= 64) {
        __syncthreads();
#pragma unroll
        for (int i = 0; i < 4; i++) {
            int id2 = t + i * 128;
            int r  = id2 >> 3;
            int c8 = (id2 & 7) * 8;
            size_t src = (size_t)(rowb + c + r) * 256 + hk * HDc + c8;
            *(uint4*)&Kt[r][c8] = *(const uint4*)(g_ksh + src);
            uint4 vv = *(const uint4*)(g_vsh + src);
            const __half* hv = (const __half*)&vv;
#pragma unroll
            for (int j = 0; j < 8; j++) Vt[c8 + j][r] = hv[j];
        }
        __syncthreads();

        float S[8][4];
#pragma unroll
        for (int nt = 0; nt < 8; nt++)
#pragma unroll
            for (int e = 0; e < 4; e++) S[nt][e] = 0.f;
#pragma unroll
        for (int kk = 0; kk < 4; kk++)
#pragma unroll
            for (int nt = 0; nt < 8; nt++) {
                const __half* kp = &Kt[nt * 8 + g][kk * 16 + tig * 2];
                uint32_t b0 = *(const uint32_t*)kp;
                uint32_t b1 = *(const uint32_t*)(kp + 8);
                mma_f16(S[nt], qf[kk], b0, b1);
            }

        float mt0 = -1e30f, mt1 = -1e30f;
#pragma unroll
        for (int nt = 0; nt < 8; nt++) {
            int key = c + nt * 8 + tig * 2;
            float s0 = (key     <= qr0 && key     > qr0 - WSSM) ? S[nt][0] * 0.125f : -1e30f;
            float s1 = (key + 1 <= qr0 && key + 1 > qr0 - WSSM) ? S[nt][1] * 0.125f : -1e30f;
            float s2 = (key     <= qr1 && key     > qr1 - WSSM) ? S[nt][2] * 0.125f : -1e30f;
            float s3 = (key + 1 <= qr1 && key + 1 > qr1 - WSSM) ? S[nt][3] * 0.125f : -1e30f;
            S[nt][0] = s0; S[nt][1] = s1; S[nt][2] = s2; S[nt][3] = s3;
            mt0 = fmaxf(mt0, fmaxf(s0, s1));
            mt1 = fmaxf(mt1, fmaxf(s2, s3));
        }
        mt0 = fmaxf(mt0, __shfl_xor_sync(0xffffffffu, mt0, 1));
        mt0 = fmaxf(mt0, __shfl_xor_sync(0xffffffffu, mt0, 2));
        mt1 = fmaxf(mt1, __shfl_xor_sync(0xffffffffu, mt1, 1));
        mt1 = fmaxf(mt1, __shfl_xor_sync(0xffffffffu, mt1, 2));

        float nm0 = fmaxf(m0, mt0), nm1 = fmaxf(m1, mt1);
        float cr0 = __expf(m0 - nm0), cr1 = __expf(m1 - nm1);
        m0 = nm0; m1 = nm1;

        float ps0 = 0.f, ps1 = 0.f;
#pragma unroll
        for (int nt = 0; nt < 8; nt++) {
            S[nt][0] = __expf(S[nt][0] - nm0);
            S[nt][1] = __expf(S[nt][1] - nm0);
            S[nt][2] = __expf(S[nt][2] - nm1);
            S[nt][3] = __expf(S[nt][3] - nm1);
            ps0 += S[nt][0] + S[nt][1];
            ps1 += S[nt][2] + S[nt][3];
        }
        ps0 += __shfl_xor_sync(0xffffffffu, ps0, 1);
        ps0 += __shfl_xor_sync(0xffffffffu, ps0, 2);
        ps1 += __shfl_xor_sync(0xffffffffu, ps1, 1);
        ps1 += __shfl_xor_sync(0xffffffffu, ps1, 2);
        l0 = l0 * cr0 + ps0;
        l1 = l1 * cr1 + ps1;

#pragma unroll
        for (int nt = 0; nt < 8; nt++) {
            O[nt][0] *= cr0; O[nt][1] *= cr0;
            O[nt][2] *= cr1; O[nt][3] *= cr1;
        }

#pragma unroll
        for (int kk = 0; kk < 4; kk++) {
            uint32_t pf[4];
            __half2 h0 = __floats2half2_rn(S[2 * kk][0],     S[2 * kk][1]);
            __half2 h1 = __floats2half2_rn(S[2 * kk][2],     S[2 * kk][3]);
            __half2 h2 = __floats2half2_rn(S[2 * kk + 1][0], S[2 * kk + 1][1]);
            __half2 h3 = __floats2half2_rn(S[2 * kk + 1][2], S[2 * kk + 1][3]);
            pf[0] = *(uint32_t*)&h0; pf[1] = *(uint32_t*)&h1;
            pf[2] = *(uint32_t*)&h2; pf[3] = *(uint32_t*)&h3;
#pragma unroll
            for (int nt = 0; nt < 8; nt++) {
                const __half* vp = &Vt[nt * 8 + g][kk * 16 + tig * 2];
                uint32_t b0 = *(const uint32_t*)vp;
                uint32_t b1 = *(const uint32_t*)(vp + 8);
                mma_f16(O[nt], pf, b0, b1);
            }
        }
    }

    float i0 = 1.f / l0, i1 = 1.f / l1;
    __half* ob = g_oh + (size_t)rowb * 1024 + h * HDc;
#pragma unroll
    for (int nt = 0; nt < 8; nt++) {
        *(__half2*)(ob + (size_t)qr0 * 1024 + nt * 8 + tig * 2) =
            __floats2half2_rn(O[nt][0] * i0, O[nt][1] * i0);
        *(__half2*)(ob + (size_t)qr1 * 1024 + nt * 8 + tig * 2) =
            __floats2half2_rn(O[nt][2] * i1, O[nt][3] * i1);
    }
}

// ---------------- host launcher ----------------
extern "C" void kernel_launch(void* const* d_in, const int* in_sizes, int n_in,
                              void* d_out, int out_size) {
    const float* hidden      = (const float*)d_in[0];
    const float* pre_norm_w  = (const float*)d_in[1];
    const float* in_proj_w   = (const float*)d_in[2];
    const float* conv_w      = (const float*)d_in[3];
    const float* conv_b      = (const float*)d_in[4];
    const float* x_proj_w    = (const float*)d_in[5];
    const float* dt_proj_w   = (const float*)d_in[6];
    const float* dt_proj_b   = (const float*)d_in[7];
    const float* A_log       = (const float*)d_in[8];
    const float* Dp          = (const float*)d_in[9];
    const float* out_proj_w  = (const float*)d_in[10];
    const float* ssm_norm_w  = (const float*)d_in[11];
    const float* q_w         = (const float*)d_in[12];
    const float* k_w         = (const float*)d_in[13];
    const float* v_w         = (const float*)d_in[14];
    const float* o_w         = (const float*)d_in[15];
    const float* mlp_norm_w  = (const float*)d_in[16];
    const float* gate_w      = (const float*)d_in[17];
    const float* down_w      = (const float*)d_in[18];
    float* out = (float*)d_out;

    const int smem128 = (BM * PADH + 128 * PADH) * STAGES * 2;
    const int smem64  = (BM * PADH + 64 * PADH) * STAGES * 2;
    cudaFuncSetAttribute(gemm_h<128, OP_HALF,  false>, cudaFuncAttributeMaxDynamicSharedMemorySize, smem128);
    cudaFuncSetAttribute(gemm_h<128, OP_SPLUS, false>, cudaFuncAttributeMaxDynamicSharedMemorySize, smem128);
    cudaFuncSetAttribute(gemm_h<128, OP_SWIGLU,false>, cudaFuncAttributeMaxDynamicSharedMemorySize, smem128);
    cudaFuncSetAttribute(gemm_h<64,  OP_HALF,  true >, cudaFuncAttributeMaxDynamicSharedMemorySize, smem64);
    cudaFuncSetAttribute(gemm_h<64,  OP_NONE,  false>, cudaFuncAttributeMaxDynamicSharedMemorySize, smem64);
    cudaFuncSetAttribute(gemm_h<64,  OP_ADDC,  false>, cudaFuncAttributeMaxDynamicSharedMemorySize, smem64);
    cudaFuncSetAttribute(fused_scan_attn, cudaFuncAttributeMaxDynamicSharedMemorySize, FUS_SMEM);

    __half *hs, *xsh, *proj_h, *y, *ssmst, *oh, *x2, *hm;
    __half *wbig, *wxp, *wdt, *wop, *wkv, *wo, *wg, *wd;
    float *xs, *dt, *tmp, *ssmres, *kvssm, *mlpres;
    cudaGetSymbolAddress((void**)&hs, g_hs);
    cudaGetSymbolAddress((void**)&xs, g_xs);
    cudaGetSymbolAddress((void**)&xsh, g_xsh);
    cudaGetSymbolAddress((void**)&proj_h, g_proj_h);
    cudaGetSymbolAddress((void**)&dt, g_dt);
    cudaGetSymbolAddress((void**)&y, g_y);
    cudaGetSymbolAddress((void**)&tmp, g_tmp);
    cudaGetSymbolAddress((void**)&ssmres, g_ssmres);
    cudaGetSymbolAddress((void**)&ssmst, g_ssmst);
    cudaGetSymbolAddress((void**)&kvssm, g_kvssm);
    cudaGetSymbolAddress((void**)&oh, g_oh);
    cudaGetSymbolAddress((void**)&mlpres, g_mlpres);
    cudaGetSymbolAddress((void**)&x2, g_x2);
    cudaGetSymbolAddress((void**)&hm, g_hm);
    cudaGetSymbolAddress((void**)&wbig, g_wbig);
    cudaGetSymbolAddress((void**)&wxp, g_wxp);
    cudaGetSymbolAddress((void**)&wdt, g_wdt);
    cudaGetSymbolAddress((void**)&wop, g_wop);
    cudaGetSymbolAddress((void**)&wkv, g_wkv);
    cudaGetSymbolAddress((void**)&wo, g_wo);
    cudaGetSymbolAddress((void**)&wg, g_wg);
    cudaGetSymbolAddress((void**)&wd, g_wd);
    __half* xzq;
    cudaGetSymbolAddress((void**)&xzq, g_xzq);

    // 1. fused prep + prenorm
    k_prep_norm<<<Mrows + PREP_BLOCKS, 256>>>(hidden, pre_norm_w, in_proj_w, q_w, k_w,
                                              v_w, gate_w, x_proj_w, dt_proj_w,
                                              out_proj_w, o_w, down_w);
    // 2. fused xz|q|k|v (2048 x 5632, K=1024) -> half
    gemm_h<128, OP_HALF, false><<<dim3(FUSN / 128, Mrows / BM), 128, smem128>>>(
        hs, wbig, xzq, nullptr, FUSN, Hc, Hc, Hc);
    // 3. fused conv + postprocA (q/k_att rotary, v_att copy)
    k_conv_ppa<<<CONV_BLOCKS + PPA_BLOCKS, 256>>>(conv_w, conv_b);
    // 4. x_proj -> half
    gemm_h<64, OP_HALF, true><<<dim3(2, Mrows / BM), 128, smem64>>>(
        xsh, wxp, proj_h, nullptr, PROJW, Ic, Ic, Ic);
    // 5. dt GEMM with fused bias+softplus
    gemm_h<128, OP_SPLUS, false><<<dim3(Ic / 128, Mrows / BM), 128, smem128>>>(
        proj_h, wdt, dt, dt_proj_b, Ic, Rc, PROJW, Rc);
    // 6. fused scan || attn_a
    fused_scan_attn<<<SCAN_BLOCKS + ATTA_BLOCKS, 256, FUS_SMEM>>>(A_log, Dp);
    // 7. out_proj; residual + norm
    gemm_h<64, OP_NONE, false><<<dim3(Hc / 64, Mrows / BM), 128, smem64>>>(
        y, wop, tmp, nullptr, Hc, Ic, Ic, Ic);
    resid_rms<<<Mrows, 256>>>(tmp, hidden, ssm_norm_w, ssmres, ssmst);
    // 8. kv_ssm
    gemm_h<64, OP_NONE, false><<<dim3(KVSLD / 64, Mrows / BM), 128, smem64>>>(
        ssmst, wkv, kvssm, nullptr, KVSLD, Hc, Hc, Hc);
    // 9. postprocB (k_ssm rotary + v_ssm copy)
    postprocB<<<(Mrows * PPB_W) / 256, 256>>>();
    // 10. attn_b (ssm window + merge)
    attn_b<<<dim3(Sc / 64, NHc, Bc), 128>>>();
    // 11. o proj; residual + norm
    gemm_h<64, OP_NONE, false><<<dim3(Hc / 64, Mrows / BM), 128, smem64>>>(
        oh, wo, tmp, nullptr, Hc, NHc * HDc, NHc * HDc, NHc * HDc);
    resid_rms<<<Mrows, 256>>>(tmp, ssmres, mlp_norm_w, mlpres, x2);
    // 12. MLP
    gemm_h<128, OP_SWIGLU, false><<<dim3(GATEN / 128, Mrows / BM), 128, smem128>>>(
        x2, wg, hm, nullptr, GATEN, Hc, Hc, Hc);
    gemm_h<64, OP_ADDC, false><<<dim3(Hc / 64, Mrows / BM), 128, smem64>>>(
        hm, wd, out, mlpres, Hc, IMc, IMc, IMc);
}

// round 17
// speedup vs baseline: 1.0436x; 1.0436x over previous
#include <cuda_runtime.h>
#include <cuda_fp16.h>
#include <math.h>
#include <stdint.h>

// ---------------- problem constants ----------------
#define Bc   2
#define Sc   1024
#define Hc   1024
#define Ic   2048
#define Nst  16
#define Rc   64
#define Kcv  4
#define NHc  16
#define NKVc 4
#define HDc  64
#define WATT 512
#define WSSM 128
#define IMc  2816
#define Mrows (Bc*Sc)
#define EPSc  1e-6f
#define PROJW (Rc + 2*Nst)   // 96
#define FUSN  5632
#define KVSLD 512
#define GATEN 5632
#define XP_KS 8              // split-K factor for x_proj
#define PROJSZ (Mrows*PROJW)

// ---------------- scratch ----------------
__device__ __half g_hs[Mrows*Hc];
__device__ __half g_xzq[Mrows*FUSN];
__device__ float  g_xs[Mrows*Ic];
__device__ __half g_xsh[Mrows*Ic];
__device__ float  g_projp[XP_KS*PROJSZ];
__device__ __half g_proj_h[PROJSZ];
__device__ float  g_dt[Mrows*Ic];
__device__ __half g_y[Mrows*Ic];
__device__ float  g_tmp[Mrows*Hc];
__device__ float  g_ssmres[Mrows*Hc];
__device__ __half g_ssmst[Mrows*Hc];
__device__ float  g_kvssm[Mrows*KVSLD];
__device__ __half g_oh[Mrows*NHc*HDc];
__device__ float  g_mlpres[Mrows*Hc];
__device__ __half g_x2[Mrows*Hc];
__device__ __half g_hm[Mrows*IMc];
// compact half attention operands
__device__ __half g_qh[Mrows*NHc*HDc];
__device__ __half g_kah[Mrows*NKVc*HDc];
__device__ __half g_ksh[Mrows*NKVc*HDc];
__device__ __half g_vah[Mrows*NKVc*HDc];
__device__ __half g_vsh[Mrows*NKVc*HDc];
// half weights
__device__ __half g_wbig[FUSN*Hc];
__device__ __half g_wxp[PROJW*Ic];
__device__ __half g_wdt[Ic*Rc];
__device__ __half g_wop[Hc*Ic];
__device__ __half g_wkv[KVSLD*Hc];
__device__ __half g_wo[Hc*NHc*HDc];
__device__ __half g_wg[GATEN*Hc];
__device__ __half g_wd[Hc*IMc];

__device__ __forceinline__ float fsig(float x) { return 1.f / (1.f + __expf(-x)); }

// ---------------- fp16 MMA GEMM ----------------
#define BM 128
#define BK 32
#define PADH 40
#define STAGES 4

#define OP_NONE   0
#define OP_HALF   1
#define OP_SPLUS  2
#define OP_SWIGLU 3
#define OP_ADDC   4

__device__ __forceinline__ void cp16(uint32_t dst, const void* src, int ssize) {
    asm volatile("cp.async.cg.shared.global [%0], [%1], 16, %2;\n"
                 :: "r"(dst), "l"(src), "r"(ssize));
}
__device__ __forceinline__ void mma_f16(float* c, const uint32_t* a, uint32_t b0, uint32_t b1) {
    asm volatile("mma.sync.aligned.m16n8k16.row.col.f32.f16.f16.f32 "
                 "{%0,%1,%2,%3}, {%4,%5,%6,%7}, {%8,%9}, {%0,%1,%2,%3};\n"
                 : "+f"(c[0]), "+f"(c[1]), "+f"(c[2]), "+f"(c[3])
                 : "r"(a[0]), "r"(a[1]), "r"(a[2]), "r"(a[3]), "r"(b0), "r"(b1));
}

template<int BNT, int OP, bool NG, bool KS = false>
__global__ __launch_bounds__(128, 2)
void gemm_h(const __half* __restrict__ A, const __half* __restrict__ Bw,
            void* __restrict__ Cv, const float* __restrict__ aux,
            int Ndim, int Kdim, int lda, int ldb) {
    constexpr int NI  = BNT / 16;
    constexpr int ASZ = BM * PADH;
    constexpr int BSZ = BNT * PADH;
    constexpr int STG = ASZ + BSZ;
    extern __shared__ __half smh[];
    const int t    = threadIdx.x;
    const int bm   = blockIdx.y * BM;
    const int bn   = blockIdx.x * BNT;
    if (KS) {
        A  += (size_t)blockIdx.z * Kdim;
        Bw += (size_t)blockIdx.z * Kdim;
        Cv  = (void*)((float*)Cv + (size_t)blockIdx.z * gridDim.y * BM * Ndim);
    }
    const int warp = t >> 5, lane = t & 31;
    const int wm   = (warp & 1) * 64;
    const int wn   = (warp >> 1) * (BNT / 2);
    const int gid  = lane >> 2;
    const int tig  = lane & 3;
    const uint32_t smem_base = (uint32_t)__cvta_generic_to_shared(smh);

    float acc[4][NI][4];
#pragma unroll
    for (int mi = 0; mi < 4; mi++)
#pragma unroll
        for (int ni = 0; ni < NI; ni++)
#pragma unroll
            for (int j = 0; j < 4; j++) acc[mi][ni][j] = 0.f;

    const int niters = Kdim / BK;

    auto load_tile = [&](int slot, int k0) {
        uint32_t aOff = smem_base + slot * STG * 2;
        uint32_t bOff = aOff + ASZ * 2;
#pragma unroll
        for (int i = 0; i < 4; i++) {
            int id = t + i * 128;
            int r  = id >> 2;
            int kq = (id & 3) * 8;
            cp16(aOff + (r * PADH + kq) * 2, A + (size_t)(bm + r) * lda + k0 + kq, 16);
        }
#pragma unroll
        for (int i = 0; i < BNT / 32; i++) {
            int id = t + i * 128;
            int r  = id >> 2;
            int kq = (id & 3) * 8;
            int ok = 1;
            int br = bn + r;
            if (NG) ok = (br < Ndim);
            cp16(bOff + (r * PADH + kq) * 2,
                 Bw + (size_t)(NG ? (ok ? br : 0) : br) * ldb + k0 + kq, ok ? 16 : 0);
        }
    };

#pragma unroll
    for (int s = 0; s < STAGES - 1; s++) {
        if (s < niters) load_tile(s, s * BK);
        asm volatile("cp.async.commit_group;\n");
    }

    int cslot = 0, nslot = STAGES - 1;
    for (int it = 0; it < niters; it++) {
        asm volatile("cp.async.wait_group %0;\n" :: "n"(STAGES - 2));
        __syncthreads();
        int nk = it + STAGES - 1;
        if (nk < niters) load_tile(nslot, nk * BK);
        asm volatile("cp.async.commit_group;\n");
        if (++nslot == STAGES) nslot = 0;

        const __half* Ab = smh + cslot * STG;
        const __half* Bb = Ab + ASZ;
        if (++cslot == STAGES) cslot = 0;
#pragma unroll
        for (int kk = 0; kk < 2; kk++) {
            int kb = kk * 16;
            uint32_t afr[4][4];
#pragma unroll
            for (int mi = 0; mi < 4; mi++) {
                const __half* ab = Ab + (wm + mi * 16 + gid) * PADH + kb + tig * 2;
                afr[mi][0] = *(const uint32_t*)(ab);
                afr[mi][1] = *(const uint32_t*)(ab + 8 * PADH);
                afr[mi][2] = *(const uint32_t*)(ab + 8);
                afr[mi][3] = *(const uint32_t*)(ab + 8 * PADH + 8);
            }
#pragma unroll
            for (int ni = 0; ni < NI; ni++) {
                const __half* bb = Bb + (wn + ni * 8 + gid) * PADH + kb + tig * 2;
                uint32_t b0 = *(const uint32_t*)(bb);
                uint32_t b1 = *(const uint32_t*)(bb + 8);
#pragma unroll
                for (int mi = 0; mi < 4; mi++)
                    mma_f16(acc[mi][ni], afr[mi], b0, b1);
            }
        }
    }

    float*  Cf = (float*)Cv;
    __half* Ch = (__half*)Cv;
#pragma unroll
    for (int mi = 0; mi < 4; mi++) {
        int rbase = bm + wm + mi * 16 + gid;
#pragma unroll
        for (int ni = 0; ni < NI; ni++) {
            int c0 = bn + wn + ni * 8 + tig * 2;
            if (NG && c0 >= Ndim) continue;
#pragma unroll
            for (int half_ = 0; half_ < 2; half_++) {
                int r0 = rbase + half_ * 8;
                float a0 = acc[mi][ni][half_ * 2 + 0];
                float a1 = acc[mi][ni][half_ * 2 + 1];
                if (OP == OP_NONE) {
                    *(float2*)(Cf + (size_t)r0 * Ndim + c0) = make_float2(a0, a1);
                } else if (OP == OP_HALF) {
                    *(__half2*)(Ch + (size_t)r0 * Ndim + c0) = __floats2half2_rn(a0, a1);
                } else if (OP == OP_SPLUS) {
                    float x0 = a0 + aux[c0], x1 = a1 + aux[c0 + 1];
                    x0 = (x0 > 20.f) ? x0 : __logf(1.f + __expf(x0));
                    x1 = (x1 > 20.f) ? x1 : __logf(1.f + __expf(x1));
                    *(float2*)(Cf + (size_t)r0 * Ndim + c0) = make_float2(x0, x1);
                } else if (OP == OP_SWIGLU) {
                    float sv = a0 * fsig(a0) * a1;
                    Ch[(size_t)r0 * IMc + (c0 >> 1)] = __float2half_rn(sv);
                } else if (OP == OP_ADDC) {
                    float2 r = *(const float2*)(aux + (size_t)r0 * Ndim + c0);
                    *(float2*)(Cf + (size_t)r0 * Ndim + c0) =
                        make_float2(a0 + r.x, a1 + r.y);
                }
            }
        }
    }
}

// ---------------- split-K reduce: g_projp[8] -> g_proj_h ----------------
__global__ void reduce_proj() {
    int idx = blockIdx.x * 256 + threadIdx.x;
    if (idx >= PROJSZ) return;
    float s = 0.f;
#pragma unroll
    for (int z = 0; z < XP_KS; z++) s += g_projp[(size_t)z * PROJSZ + idx];
    g_proj_h[idx] = __float2half_rn(s);
}

// ---------------- fused prep + prenorm ----------------
#define W0 (FUSN*Hc)
#define R1 (KVSLD*Hc)
#define R2 (R1 + GATEN*Hc)
#define R3 (R2 + PROJW*Ic)
#define R4 (R3 + Ic*Rc)
#define R5 (R4 + Hc*Ic)
#define R6 (R5 + Hc*NHc*HDc)
#define R7 (R6 + Hc*IMc)
#define PREP_BLOCKS ((W0 + R7 + 255) / 256)

__global__ void k_prep_norm(const float* __restrict__ hidden, const float* __restrict__ pnw,
                            const float* __restrict__ ipw, const float* __restrict__ qw,
                            const float* __restrict__ kw, const float* __restrict__ vw,
                            const float* __restrict__ gw, const float* __restrict__ xpw,
                            const float* __restrict__ dtw, const float* __restrict__ opw,
                            const float* __restrict__ ow, const float* __restrict__ dw) {
    if (blockIdx.x < Mrows) {
        int row = blockIdx.x;
        int t   = threadIdx.x;
        const float* ap = hidden + (size_t)row * Hc;
        float v[4];
        float ss = 0.f;
#pragma unroll
        for (int i = 0; i < 4; i++) {
            int c = t + i * 256;
            float x = ap[c];
            v[i] = x;
            ss += x * x;
        }
#pragma unroll
        for (int off = 16; off; off >>= 1) ss += __shfl_xor_sync(0xffffffffu, ss, off);
        __shared__ float sred[8];
        __shared__ float sscale;
        if ((t & 31) == 0) sred[t >> 5] = ss;
        __syncthreads();
        if (t == 0) {
            float tot = 0.f;
            for (int i = 0; i < 8; i++) tot += sred[i];
            sscale = rsqrtf(tot * (1.f / Hc) + EPSc);
        }
        __syncthreads();
        float scale = sscale;
        __half* no = g_hs + (size_t)row * Hc;
#pragma unroll
        for (int i = 0; i < 4; i++) {
            int c = t + i * 256;
            no[c] = __float2half_rn(v[i] * scale * pnw[c]);
        }
        return;
    }
    int idx = (blockIdx.x - Mrows) * 256 + threadIdx.x;
    if (idx >= W0 + R7) return;
    if (idx < W0) {
        int row = idx >> 10, col = idx & 1023;
        float v;
        if (row < 4096)      v = ipw[idx];
        else if (row < 5120) v = qw[(row - 4096) * Hc + col];
        else if (row < 5376) v = kw[(row - 5120) * Hc + col];
        else                 v = vw[(row - 5376) * Hc + col];
        g_wbig[idx] = __float2half_rn(v);
        return;
    }
    idx -= W0;
    if (idx < R1) {
        int row = idx >> 10, col = idx & 1023;
        float v = (row < 256) ? kw[row * Hc + col] : vw[(row - 256) * Hc + col];
        g_wkv[idx] = __float2half_rn(v);
    } else if (idx < R2) {
        int i = idx - R1;
        int row = i >> 10, col = i & 1023;
        int f = row >> 1;
        int src = (row & 1) ? (IMc + f) : f;
        g_wg[i] = __float2half_rn(gw[src * Hc + col]);
    } else if (idx < R3) {
        int i = idx - R2; g_wxp[i] = __float2half_rn(xpw[i]);
    } else if (idx < R4) {
        int i = idx - R3; g_wdt[i] = __float2half_rn(dtw[i]);
    } else if (idx < R5) {
        int i = idx - R4; g_wop[i] = __float2half_rn(opw[i]);
    } else if (idx < R6) {
        int i = idx - R5; g_wo[i] = __float2half_rn(ow[i]);
    } else {
        int i = idx - R6; g_wd[i] = __float2half_rn(dw[i]);
    }
}

// ---------------- RMSNorm (residual variant) ----------------
__global__ void resid_rms(const float* __restrict__ a, const float* __restrict__ r,
                          const float* __restrict__ w, float* __restrict__ res_out,
                          __half* __restrict__ nrm_out) {
    int row = blockIdx.x;
    int t   = threadIdx.x;
    const float* ap = a + (size_t)row * Hc;
    const float* rp = r + (size_t)row * Hc;
    float v[4];
    float ss = 0.f;
#pragma unroll
    for (int i = 0; i < 4; i++) {
        int c = t + i * 256;
        float x = ap[c] + rp[c];
        v[i] = x;
        ss += x * x;
    }
#pragma unroll
    for (int off = 16; off; off >>= 1) ss += __shfl_xor_sync(0xffffffffu, ss, off);
    __shared__ float sred[8];
    __shared__ float sscale;
    if ((t & 31) == 0) sred[t >> 5] = ss;
    __syncthreads();
    if (t == 0) {
        float tot = 0.f;
        for (int i = 0; i < 8; i++) tot += sred[i];
        sscale = rsqrtf(tot * (1.f / Hc) + EPSc);
    }
    __syncthreads();
    float scale = sscale;
    float* ro = res_out + (size_t)row * Hc;
    __half* no = nrm_out + (size_t)row * Hc;
#pragma unroll
    for (int i = 0; i < 4; i++) {
        int c = t + i * 256;
        ro[c] = v[i];
        no[c] = __float2half_rn(v[i] * scale * w[c]);
    }
}

// ---------------- fused conv + postprocA ----------------
#define CONV_BLOCKS ((Mrows * Ic) / 256)
#define PPA_W 896
#define PPA_BLOCKS ((Mrows * PPA_W) / 256)
__global__ void k_conv_ppa(const float* __restrict__ cw, const float* __restrict__ cb) {
    if (blockIdx.x < CONV_BLOCKS) {
        int idx = blockIdx.x * 256 + threadIdx.x;
        int row = idx / Ic;
        int i   = idx - row * Ic;
        int b   = row / Sc;
        int s   = row - b * Sc;
        float acc = cb[i];
#pragma unroll
        for (int k = 0; k < Kcv; k++) {
            int sp = s + k - (Kcv - 1);
            if (sp >= 0)
                acc += cw[i * Kcv + k] *
                       __half2float(g_xzq[(size_t)(b * Sc + sp) * FUSN + i]);
        }
        float r = acc * fsig(acc);
        g_xs[idx]  = r;
        g_xsh[idx] = __float2half_rn(r);
        return;
    }
    int idx = (blockIdx.x - CONV_BLOCKS) * 256 + threadIdx.x;
    int r   = idx / PPA_W;
    int rem = idx - r * PPA_W;
    int s   = r % Sc;
    if (rem < 512) {
        int head = rem >> 5, j = rem & 31;
        float inv = __expf(-((float)(2 * j) / 64.f) * __logf(10000.0f));
        float sn, cs; __sincosf((float)s * inv, &sn, &cs);
        const __half* bi = g_xzq + (size_t)r * FUSN + 4096 + head * HDc;
        __half* bo = g_qh + (size_t)r * 1024 + head * HDc;
        float x1 = __half2float(bi[j]), x2 = __half2float(bi[j + 32]);
        bo[j]      = __float2half_rn(x1 * cs - x2 * sn);
        bo[j + 32] = __float2half_rn(x2 * cs + x1 * sn);
    } else if (rem < 640) {
        int q = rem - 512;
        int head = q >> 5, j = q & 31;
        float inv = __expf(-((float)(2 * j) / 64.f) * __logf(10000.0f));
        float sn, cs; __sincosf((float)s * inv, &sn, &cs);
        const __half* bi = g_xzq + (size_t)r * FUSN + 5120 + head * HDc;
        __half* bo = g_kah + (size_t)r * 256 + head * HDc;
        float x1 = __half2float(bi[j]), x2 = __half2float(bi[j + 32]);
        bo[j]      = __float2half_rn(x1 * cs - x2 * sn);
        bo[j + 32] = __float2half_rn(x2 * cs + x1 * sn);
    } else {
        int col = rem - 640;
        g_vah[r * 256 + col] = g_xzq[(size_t)r * FUSN + 5376 + col];
    }
}

// ---------------- postprocB ----------------
#define PPB_W 384
__global__ void postprocB() {
    int idx = blockIdx.x * 256 + threadIdx.x;
    int r   = idx / PPB_W;
    int rem = idx - r * PPB_W;
    int s   = r % Sc;
    if (rem < 128) {
        int head = rem >> 5, j = rem & 31;
        float inv = __expf(-((float)(2 * j) / 64.f) * __logf(10000.0f));
        float sn, cs; __sincosf((float)s * inv, &sn, &cs);
        const float* bi = g_kvssm + (size_t)r * KVSLD + head * HDc;
        __half* bo = g_ksh + (size_t)r * 256 + head * HDc;
        float x1 = bi[j], x2 = bi[j + 32];
        bo[j]      = __float2half_rn(x1 * cs - x2 * sn);
        bo[j + 32] = __float2half_rn(x2 * cs + x1 * sn);
    } else {
        int col = rem - 128;
        g_vsh[r * 256 + col] =
            __float2half_rn(g_kvssm[(size_t)r * KVSLD + 256 + col]);
    }
}

// ---------------- selective scan v2 ----------------
#define SCH 64
__global__ __launch_bounds__(256) void scan2(const float* __restrict__ A_log,
                                             const float* __restrict__ Dp) {
    __shared__ float  sdt[2][SCH][16];
    __shared__ float  sxs[2][SCH][16];
    __shared__ __half szz[2][SCH][16];
    __shared__ __half sbc[2][SCH][32];
    __shared__ __half sy[SCH][16];
    int t  = threadIdx.x;
    int gi0 = blockIdx.x * 16;
    int b   = gi0 / Ic;
    int i0  = gi0 - b * Ic;
    int rowb = b * Sc;
    int c = t >> 4, n = t & 15;
    int i = i0 + c;
    float An = -__expf(A_log[i * Nst + n]);
    float Dv = Dp[i];

    int lrow = t >> 2, lq = t & 3;
    auto load_chunk = [&](int buf, int s0) {
        size_t gr = (size_t)(rowb + s0 + lrow);
        cp16((uint32_t)__cvta_generic_to_shared(&sdt[buf][lrow][lq * 4]),
             g_dt + gr * Ic + i0 + lq * 4, 16);
        cp16((uint32_t)__cvta_generic_to_shared(&sxs[buf][lrow][lq * 4]),
             g_xs + gr * Ic + i0 + lq * 4, 16);
        if (lq < 2)
            cp16((uint32_t)__cvta_generic_to_shared(&szz[buf][lrow][lq * 8]),
                 g_xzq + gr * FUSN + Ic + i0 + lq * 8, 16);
        cp16((uint32_t)__cvta_generic_to_shared(&sbc[buf][lrow][lq * 8]),
             g_proj_h + gr * PROJW + Rc + lq * 8, 16);
    };

    load_chunk(0, 0);
    asm volatile("cp.async.commit_group;\n");

    float h = 0.f;
    for (int ch = 0; ch < Sc / SCH; ch++) {
        int buf = ch & 1;
        if (ch + 1 < Sc / SCH) {
            load_chunk(buf ^ 1, (ch + 1) * SCH);
            asm volatile("cp.async.commit_group;\n");
            asm volatile("cp.async.wait_group 1;\n");
        } else {
            asm volatile("cp.async.wait_group 0;\n");
        }
        __syncthreads();
#pragma unroll 4
        for (int s = 0; s < SCH; s++) {
            float dtv = sdt[buf][s][c];
            float xsv = sxs[buf][s][c];
            float Bn  = __half2float(sbc[buf][s][n]);
            float Cn  = __half2float(sbc[buf][s][16 + n]);
            h = h * __expf(dtv * An) + dtv * Bn * xsv;
            float v = h * Cn;
            v += __shfl_xor_sync(0xffffffffu, v, 8);
            v += __shfl_xor_sync(0xffffffffu, v, 4);
            v += __shfl_xor_sync(0xffffffffu, v, 2);
            v += __shfl_xor_sync(0xffffffffu, v, 1);
            if (n == 0) {
                float z = __half2float(szz[buf][s][c]);
                sy[s][c] = __float2half_rn((v + Dv * xsv) * (z * fsig(z)));
            }
        }
        __syncthreads();
        if (t < 128) {
            int row = t >> 1, part = (t & 1) * 8;
            *(uint4*)(g_y + (size_t)(rowb + ch * SCH + row) * Ic + i0 + part) =
                *(const uint4*)&sy[row][part];
        }
    }
}

// ---------------- attn4: FA2-style MMA attention ----------------
__global__ __launch_bounds__(128) void attn4() {
    __shared__ __half Kt[64][72];
    __shared__ __half Vt[64][72];
    int t = threadIdx.x, w = t >> 5, lane = t & 31;
    int g = lane >> 2, tig = lane & 3;
    int q0 = blockIdx.x * 64, h = blockIdx.y, b = blockIdx.z;
    int rowb = b * Sc, hk = h >> 2;
    int qr0 = q0 + w * 16 + g;
    int qr1 = qr0 + 8;

    uint32_t qf[4][4];
    {
        const __half* qb = g_qh + (size_t)rowb * 1024 + h * HDc;
#pragma unroll
        for (int kk = 0; kk < 4; kk++) {
            const __half* r0 = qb + (size_t)qr0 * 1024 + kk * 16 + tig * 2;
            const __half* r1 = qb + (size_t)qr1 * 1024 + kk * 16 + tig * 2;
            qf[kk][0] = *(const uint32_t*)(r0);
            qf[kk][1] = *(const uint32_t*)(r1);
            qf[kk][2] = *(const uint32_t*)(r0 + 8);
            qf[kk][3] = *(const uint32_t*)(r1 + 8);
        }
    }

    float O[8][4];
#pragma unroll
    for (int nt = 0; nt < 8; nt++)
#pragma unroll
        for (int e = 0; e < 4; e++) O[nt][e] = 0.f;
    float m0 = -1e30f, m1 = -1e30f, l0 = 0.f, l1 = 0.f;

    for (int pass = 0; pass < 2; pass++) {
        const __half* kb = pass ? g_ksh : g_kah;
        const __half* vb = pass ? g_vsh : g_vah;
        int W  = pass ? WSSM : WATT;
        int cs = max(0, q0 - (W - 1)) & ~63;
        for (int c = q0; c >= cs; c -= 64) {
            __syncthreads();
#pragma unroll
            for (int i = 0; i < 4; i++) {
                int id = t + i * 128;
                int r  = id >> 3;
                int c8 = (id & 7) * 8;
                size_t src = (size_t)(rowb + c + r) * 256 + hk * HDc + c8;
                *(uint4*)&Kt[r][c8] = *(const uint4*)(kb + src);
                uint4 vv = *(const uint4*)(vb + src);
                const __half* hv = (const __half*)&vv;
#pragma unroll
                for (int j = 0; j < 8; j++) Vt[c8 + j][r] = hv[j];
            }
            __syncthreads();

            float S[8][4];
#pragma unroll
            for (int nt = 0; nt < 8; nt++)
#pragma unroll
                for (int e = 0; e < 4; e++) S[nt][e] = 0.f;
#pragma unroll
            for (int kk = 0; kk < 4; kk++)
#pragma unroll
                for (int nt = 0; nt < 8; nt++) {
                    const __half* kp = &Kt[nt * 8 + g][kk * 16 + tig * 2];
                    uint32_t b0 = *(const uint32_t*)kp;
                    uint32_t b1 = *(const uint32_t*)(kp + 8);
                    mma_f16(S[nt], qf[kk], b0, b1);
                }

            float mt0 = -1e30f, mt1 = -1e30f;
#pragma unroll
            for (int nt = 0; nt < 8; nt++) {
                int key = c + nt * 8 + tig * 2;
                float s0 = (key     <= qr0 && key     > qr0 - W) ? S[nt][0] * 0.125f : -1e30f;
                float s1 = (key + 1 <= qr0 && key + 1 > qr0 - W) ? S[nt][1] * 0.125f : -1e30f;
                float s2 = (key     <= qr1 && key     > qr1 - W) ? S[nt][2] * 0.125f : -1e30f;
                float s3 = (key + 1 <= qr1 && key + 1 > qr1 - W) ? S[nt][3] * 0.125f : -1e30f;
                S[nt][0] = s0; S[nt][1] = s1; S[nt][2] = s2; S[nt][3] = s3;
                mt0 = fmaxf(mt0, fmaxf(s0, s1));
                mt1 = fmaxf(mt1, fmaxf(s2, s3));
            }
            mt0 = fmaxf(mt0, __shfl_xor_sync(0xffffffffu, mt0, 1));
            mt0 = fmaxf(mt0, __shfl_xor_sync(0xffffffffu, mt0, 2));
            mt1 = fmaxf(mt1, __shfl_xor_sync(0xffffffffu, mt1, 1));
            mt1 = fmaxf(mt1, __shfl_xor_sync(0xffffffffu, mt1, 2));

            float nm0 = fmaxf(m0, mt0), nm1 = fmaxf(m1, mt1);
            float cr0 = __expf(m0 - nm0), cr1 = __expf(m1 - nm1);
            m0 = nm0; m1 = nm1;

            float ps0 = 0.f, ps1 = 0.f;
#pragma unroll
            for (int nt = 0; nt < 8; nt++) {
                S[nt][0] = __expf(S[nt][0] - nm0);
                S[nt][1] = __expf(S[nt][1] - nm0);
                S[nt][2] = __expf(S[nt][2] - nm1);
                S[nt][3] = __expf(S[nt][3] - nm1);
                ps0 += S[nt][0] + S[nt][1];
                ps1 += S[nt][2] + S[nt][3];
            }
            ps0 += __shfl_xor_sync(0xffffffffu, ps0, 1);
            ps0 += __shfl_xor_sync(0xffffffffu, ps0, 2);
            ps1 += __shfl_xor_sync(0xffffffffu, ps1, 1);
            ps1 += __shfl_xor_sync(0xffffffffu, ps1, 2);
            l0 = l0 * cr0 + ps0;
            l1 = l1 * cr1 + ps1;

#pragma unroll
            for (int nt = 0; nt < 8; nt++) {
                O[nt][0] *= cr0; O[nt][1] *= cr0;
                O[nt][2] *= cr1; O[nt][3] *= cr1;
            }

#pragma unroll
            for (int kk = 0; kk < 4; kk++) {
                uint32_t pf[4];
                __half2 h0 = __floats2half2_rn(S[2 * kk][0],     S[2 * kk][1]);
                __half2 h1 = __floats2half2_rn(S[2 * kk][2],     S[2 * kk][3]);
                __half2 h2 = __floats2half2_rn(S[2 * kk + 1][0], S[2 * kk + 1][1]);
                __half2 h3 = __floats2half2_rn(S[2 * kk + 1][2], S[2 * kk + 1][3]);
                pf[0] = *(uint32_t*)&h0; pf[1] = *(uint32_t*)&h1;
                pf[2] = *(uint32_t*)&h2; pf[3] = *(uint32_t*)&h3;
#pragma unroll
                for (int nt = 0; nt < 8; nt++) {
                    const __half* vp = &Vt[nt * 8 + g][kk * 16 + tig * 2];
                    uint32_t b0 = *(const uint32_t*)vp;
                    uint32_t b1 = *(const uint32_t*)(vp + 8);
                    mma_f16(O[nt], pf, b0, b1);
                }
            }
        }
    }

    float i0 = 1.f / l0, i1 = 1.f / l1;
    __half* ob = g_oh + (size_t)rowb * 1024 + h * HDc;
#pragma unroll
    for (int nt = 0; nt < 8; nt++) {
        *(__half2*)(ob + (size_t)qr0 * 1024 + nt * 8 + tig * 2) =
            __floats2half2_rn(O[nt][0] * i0, O[nt][1] * i0);
        *(__half2*)(ob + (size_t)qr1 * 1024 + nt * 8 + tig * 2) =
            __floats2half2_rn(O[nt][2] * i1, O[nt][3] * i1);
    }
}

// ---------------- host launcher ----------------
extern "C" void kernel_launch(void* const* d_in, const int* in_sizes, int n_in,
                              void* d_out, int out_size) {
    const float* hidden      = (const float*)d_in[0];
    const float* pre_norm_w  = (const float*)d_in[1];
    const float* in_proj_w   = (const float*)d_in[2];
    const float* conv_w      = (const float*)d_in[3];
    const float* conv_b      = (const float*)d_in[4];
    const float* x_proj_w    = (const float*)d_in[5];
    const float* dt_proj_w   = (const float*)d_in[6];
    const float* dt_proj_b   = (const float*)d_in[7];
    const float* A_log       = (const float*)d_in[8];
    const float* Dp          = (const float*)d_in[9];
    const float* out_proj_w  = (const float*)d_in[10];
    const float* ssm_norm_w  = (const float*)d_in[11];
    const float* q_w         = (const float*)d_in[12];
    const float* k_w         = (const float*)d_in[13];
    const float* v_w         = (const float*)d_in[14];
    const float* o_w         = (const float*)d_in[15];
    const float* mlp_norm_w  = (const float*)d_in[16];
    const float* gate_w      = (const float*)d_in[17];
    const float* down_w      = (const float*)d_in[18];
    float* out = (float*)d_out;

    const int smem128 = (BM * PADH + 128 * PADH) * STAGES * 2;
    const int smem64  = (BM * PADH + 64 * PADH) * STAGES * 2;
    cudaFuncSetAttribute(gemm_h<128, OP_HALF,  false>, cudaFuncAttributeMaxDynamicSharedMemorySize, smem128);
    cudaFuncSetAttribute(gemm_h<128, OP_SPLUS, false>, cudaFuncAttributeMaxDynamicSharedMemorySize, smem128);
    cudaFuncSetAttribute(gemm_h<128, OP_SWIGLU,false>, cudaFuncAttributeMaxDynamicSharedMemorySize, smem128);
    cudaFuncSetAttribute(gemm_h<64,  OP_NONE,  true, true>, cudaFuncAttributeMaxDynamicSharedMemorySize, smem64);
    cudaFuncSetAttribute(gemm_h<64,  OP_NONE,  false>, cudaFuncAttributeMaxDynamicSharedMemorySize, smem64);
    cudaFuncSetAttribute(gemm_h<64,  OP_ADDC,  false>, cudaFuncAttributeMaxDynamicSharedMemorySize, smem64);

    __half *hs, *xsh, *proj_h, *y, *ssmst, *oh, *x2, *hm;
    __half *wbig, *wxp, *wdt, *wop, *wkv, *wo, *wg, *wd;
    float *xs, *dt, *tmp, *ssmres, *kvssm, *mlpres, *projp;
    cudaGetSymbolAddress((void**)&hs, g_hs);
    cudaGetSymbolAddress((void**)&xs, g_xs);
    cudaGetSymbolAddress((void**)&xsh, g_xsh);
    cudaGetSymbolAddress((void**)&proj_h, g_proj_h);
    cudaGetSymbolAddress((void**)&projp, g_projp);
    cudaGetSymbolAddress((void**)&dt, g_dt);
    cudaGetSymbolAddress((void**)&y, g_y);
    cudaGetSymbolAddress((void**)&tmp, g_tmp);
    cudaGetSymbolAddress((void**)&ssmres, g_ssmres);
    cudaGetSymbolAddress((void**)&ssmst, g_ssmst);
    cudaGetSymbolAddress((void**)&kvssm, g_kvssm);
    cudaGetSymbolAddress((void**)&oh, g_oh);
    cudaGetSymbolAddress((void**)&mlpres, g_mlpres);
    cudaGetSymbolAddress((void**)&x2, g_x2);
    cudaGetSymbolAddress((void**)&hm, g_hm);
    cudaGetSymbolAddress((void**)&wbig, g_wbig);
    cudaGetSymbolAddress((void**)&wxp, g_wxp);
    cudaGetSymbolAddress((void**)&wdt, g_wdt);
    cudaGetSymbolAddress((void**)&wop, g_wop);
    cudaGetSymbolAddress((void**)&wkv, g_wkv);
    cudaGetSymbolAddress((void**)&wo, g_wo);
    cudaGetSymbolAddress((void**)&wg, g_wg);
    cudaGetSymbolAddress((void**)&wd, g_wd);
    __half* xzq;
    cudaGetSymbolAddress((void**)&xzq, g_xzq);

    // 1. fused prep + prenorm
    k_prep_norm<<<Mrows + PREP_BLOCKS, 256>>>(hidden, pre_norm_w, in_proj_w, q_w, k_w,
                                              v_w, gate_w, x_proj_w, dt_proj_w,
                                              out_proj_w, o_w, down_w);
    // 2. fused xz|q|k|v -> half
    gemm_h<128, OP_HALF, false><<<dim3(FUSN / 128, Mrows / BM), 128, smem128>>>(
        hs, wbig, xzq, nullptr, FUSN, Hc, Hc, Hc);
    // 3. fused conv + postprocA
    k_conv_ppa<<<CONV_BLOCKS + PPA_BLOCKS, 256>>>(conv_w, conv_b);
    // 4. x_proj split-K (2048 x 96, K=2048 in 8 chunks of 256)
    gemm_h<64, OP_NONE, true, true><<<dim3(2, Mrows / BM, XP_KS), 128, smem64>>>(
        xsh, wxp, projp, nullptr, PROJW, Ic / XP_KS, Ic, Ic);
    // 5. reduce partials -> proj_h
    reduce_proj<<<(PROJSZ + 255) / 256, 256>>>();
    // 6. dt GEMM with fused bias+softplus
    gemm_h<128, OP_SPLUS, false><<<dim3(Ic / 128, Mrows / BM), 128, smem128>>>(
        proj_h, wdt, dt, dt_proj_b, Ic, Rc, PROJW, Rc);
    // 7. selective scan
    scan2<<<(Bc * Ic) / 16, 256>>>(A_log, Dp);
    // 8. out_proj; residual + norm
    gemm_h<64, OP_NONE, false><<<dim3(Hc / 64, Mrows / BM), 128, smem64>>>(
        y, wop, tmp, nullptr, Hc, Ic, Ic, Ic);
    resid_rms<<<Mrows, 256>>>(tmp, hidden, ssm_norm_w, ssmres, ssmst);
    // 9. kv_ssm
    gemm_h<64, OP_NONE, false><<<dim3(KVSLD / 64, Mrows / BM), 128, smem64>>>(
        ssmst, wkv, kvssm, nullptr, KVSLD, Hc, Hc, Hc);
    // 10. postprocB
    postprocB<<<(Mrows * PPB_W) / 256, 256>>>();
    // 11. attention
    attn4<<<dim3(Sc / 64, NHc, Bc), 128>>>();
    // 12. o proj; residual + norm
    gemm_h<64, OP_NONE, false><<<dim3(Hc / 64, Mrows / BM), 128, smem64>>>(
        oh, wo, tmp, nullptr, Hc, NHc * HDc, NHc * HDc, NHc * HDc);
    resid_rms<<<Mrows, 256>>>(tmp, ssmres, mlp_norm_w, mlpres, x2);
    // 13. MLP
    gemm_h<128, OP_SWIGLU, false><<<dim3(GATEN / 128, Mrows / BM), 128, smem128>>>(
        x2, wg, hm, nullptr, GATEN, Hc, Hc, Hc);
    gemm_h<64, OP_ADDC, false><<<dim3(Hc / 64, Mrows / BM), 128, smem64>>>(
        hm, wd, out, mlpres, Hc, IMc, IMc, IMc);
}